// round 10
// baseline (speedup 1.0000x reference)
#include <cuda_runtime.h>
#include <cuda_fp16.h>
#include <math.h>
#include <stdint.h>

#define T_SEQ   2048
#define HID     4096
#define NHEAD   32
#define Q_LORA  1536
#define KV_LORA 512
#define D_NOPE  128
#define D_ROPE  64
#define D_QK    192
#define D_V     128
#define D_AUG   576
#define EPS_RMS 1e-6f

#define F_KCAUSAL 1   // K_eff = row0 + 128 (PV with zero-padded P)
#define F_SKIP    4   // skip blocks fully above causal diagonal
#define F_HALFOUT 8   // C is __half*

// ---------------- scratch (device globals) ----------------
__device__ float  g_qc    [T_SEQ * Q_LORA];
__device__ float  g_q     [T_SEQ * NHEAD * D_QK];
__device__ float  g_kva   [T_SEQ * D_AUG];
__device__ float  g_caug  [T_SEQ * D_AUG];

__device__ __half h_hs    [T_SEQ * HID];
__device__ __half h_qc    [T_SEQ * Q_LORA];
__device__ __half h_q     [T_SEQ * NHEAD * D_QK];
__device__ __half h_wuk   [KV_LORA * NHEAD * D_NOPE];            // [r][h][d]
__device__ __half h_qaug  [(size_t)NHEAD * T_SEQ * D_AUG];       // [h][t][576]
__device__ __half h_caug  [T_SEQ * D_AUG];                       // [s][576]
__device__ __half h_compT [KV_LORA * T_SEQ];                     // [r][s]
__device__ __half h_probs [(size_t)NHEAD * T_SEQ * T_SEQ];       // [h][t][s] scores->probs in place
__device__ __half h_ol    [(size_t)NHEAD * T_SEQ * KV_LORA];     // [h][t][r]
__device__ __half h_ov    [T_SEQ * NHEAD * D_V];
__device__ __half h_wqaT  [Q_LORA * HID];
__device__ __half h_wqbT  [(NHEAD*D_QK) * Q_LORA];
__device__ __half h_wkvaT [D_AUG * HID];
__device__ __half h_woT   [HID * HID];
__device__ __half h_wuvT  [NHEAD * D_V * KV_LORA];               // [h][d][r]

// ---------------- helpers ----------------
__device__ __forceinline__ uint32_t smem_u32(const void* p)
{
    uint32_t a;
    asm("{ .reg .u64 t; cvta.to.shared.u64 t, %1; cvt.u32.u64 %0, t; }" : "=r"(a) : "l"(p));
    return a;
}

__device__ __forceinline__ void mma16816(float c[4], const uint32_t a[4], const uint32_t b[2])
{
    asm volatile(
        "mma.sync.aligned.m16n8k16.row.col.f32.f16.f16.f32 "
        "{%0,%1,%2,%3}, {%4,%5,%6,%7}, {%8,%9}, {%0,%1,%2,%3};"
        : "+f"(c[0]), "+f"(c[1]), "+f"(c[2]), "+f"(c[3])
        : "r"(a[0]), "r"(a[1]), "r"(a[2]), "r"(a[3]), "r"(b[0]), "r"(b[1]));
}

#define LDSM_X4(r0, r1, r2, r3, addr) \
    asm volatile("ldmatrix.sync.aligned.m8n8.x4.shared.b16 {%0,%1,%2,%3}, [%4];" \
        : "=r"(r0), "=r"(r1), "=r"(r2), "=r"(r3) : "r"(addr))

__device__ __forceinline__ void cpa16(uint32_t dst, const void* src, int sz)
{
    asm volatile("cp.async.cg.shared.global [%0], [%1], 16, %2;"
        :: "r"(dst), "l"(src), "r"(sz) : "memory");
}

// load [128 rows][32 halves] tile (stride 40 halves): 2 threads per row
__device__ __forceinline__ void load_tile128(
    const __half* __restrict__ src, int ld, int r0, int nvalid, int k0,
    uint32_t dst, int tid)
{
    const int row = tid >> 1;
    const int half32 = (tid & 1);
    const __half* g = src + (size_t)(r0 + row) * ld + k0 + half32 * 16;
    const uint32_t d = dst + row * 80 + half32 * 32;
    const int sz = ((r0 + row) < nvalid) ? 16 : 0;
    cpa16(d,      g,     sz);
    cpa16(d + 16, g + 8, sz);
}

// load [256 rows][32 halves] tile (stride 40 halves): 1 thread per row
__device__ __forceinline__ void load_tile256(
    const __half* __restrict__ src, int ld, int r0, int nvalid, int k0,
    uint32_t dst, int tid)
{
    const int row = tid;
    const __half* g = src + (size_t)(r0 + row) * ld + k0;
    const uint32_t d = dst + row * 80;
    const int sz = ((r0 + row) < nvalid) ? 16 : 0;
    cpa16(d,      g,      sz);
    cpa16(d + 16, g + 8,  sz);
    cpa16(d + 32, g + 16, sz);
    cpa16(d + 48, g + 24, sz);
}

// ============================================================================
// hgemm: 128x128 tile (fallback for N not multiple of 256)
// ============================================================================
#define STAGE_H (128 * 40)
#define HG_SMEM (3 * STAGE_H * 2 * 2)

__global__ void __launch_bounds__(256, 2) hgemm(
    const __half* __restrict__ A, int lda, long long sA,
    const __half* __restrict__ B, int ldb, long long sB,
    void* __restrict__ Cv, int ldc, long long sC,
    int M, int N, int K, int flags)
{
    const int row0 = blockIdx.y * 128;
    const int col0 = blockIdx.x * 128;
    if ((flags & F_SKIP) && col0 > row0 + 127) return;
    A += (long long)blockIdx.z * sA;
    B += (long long)blockIdx.z * sB;

    extern __shared__ __half dsm[];
    const uint32_t baseA = smem_u32(dsm);
    const uint32_t baseB = baseA + 3 * STAGE_H * 2;

    const int tid    = threadIdx.x;
    const int lane   = tid & 31;
    const int wid    = tid >> 5;
    const int warp_m = wid >> 2;
    const int warp_n = wid & 3;
    const int lg     = lane >> 2;
    const int lt     = lane & 3;
    const int lq     = lane >> 3;
    const int lr     = lane & 7;

    const int Keff = (flags & F_KCAUSAL) ? (row0 + 128) : K;
    const int nk   = Keff >> 5;

    float acc[4][4][4];
    #pragma unroll
    for (int i = 0; i < 4; i++)
        #pragma unroll
        for (int j = 0; j < 4; j++)
            #pragma unroll
            for (int e = 0; e < 4; e++) acc[i][j][e] = 0.f;

    load_tile128(A, lda, row0, M, 0, baseA, tid);
    load_tile128(B, ldb, col0, N, 0, baseB, tid);
    asm volatile("cp.async.commit_group;" ::: "memory");
    if (nk > 1) {
        load_tile128(A, lda, row0, M, 32, baseA + STAGE_H * 2, tid);
        load_tile128(B, ldb, col0, N, 32, baseB + STAGE_H * 2, tid);
        asm volatile("cp.async.commit_group;" ::: "memory");
    }

    int sidx = 0;
    for (int i = 0; i < nk; i++) {
        if (i + 1 < nk) {
            asm volatile("cp.async.wait_group 1;" ::: "memory");
        } else {
            asm volatile("cp.async.wait_group 0;" ::: "memory");
        }
        __syncthreads();
        if (i + 2 < nk) {
            const int s2 = (sidx + 2) % 3;
            load_tile128(A, lda, row0, M, (i + 2) * 32, baseA + s2 * STAGE_H * 2, tid);
            load_tile128(B, ldb, col0, N, (i + 2) * 32, baseB + s2 * STAGE_H * 2, tid);
            asm volatile("cp.async.commit_group;" ::: "memory");
        }

        const uint32_t sA_ = baseA + sidx * STAGE_H * 2;
        const uint32_t sB_ = baseB + sidx * STAGE_H * 2;

        #pragma unroll
        for (int kk = 0; kk < 32; kk += 16) {
            uint32_t af[4][4];
            #pragma unroll
            for (int mt = 0; mt < 4; mt++) {
                const int r = warp_m * 64 + mt * 16 + (lq & 1) * 8 + lr;
                LDSM_X4(af[mt][0], af[mt][1], af[mt][2], af[mt][3],
                        sA_ + (r * 40 + kk + (lq >> 1) * 8) * 2);
            }
            uint32_t bf[2][4];
            #pragma unroll
            for (int np = 0; np < 2; np++) {
                const int n = warp_n * 32 + np * 16 + (lq >> 1) * 8 + lr;
                LDSM_X4(bf[np][0], bf[np][1], bf[np][2], bf[np][3],
                        sB_ + (n * 40 + kk + (lq & 1) * 8) * 2);
            }
            #pragma unroll
            for (int mt = 0; mt < 4; mt++)
                #pragma unroll
                for (int nt = 0; nt < 4; nt++)
                    mma16816(acc[mt][nt], af[mt], &bf[nt >> 1][(nt & 1) * 2]);
        }
        sidx = (sidx + 1) % 3;
    }

    if (flags & F_HALFOUT) {
        __half* C = (__half*)Cv + (long long)blockIdx.z * sC;
        #pragma unroll
        for (int mt = 0; mt < 4; mt++)
            #pragma unroll
            for (int nt = 0; nt < 4; nt++) {
                const int r = row0 + warp_m * 64 + mt * 16 + lg;
                const int c = col0 + warp_n * 32 + nt * 8 + 2 * lt;
                if (c + 1 < N) {
                    if (r < M)
                        *(__half2*)(C + (size_t)r * ldc + c) =
                            __floats2half2_rn(acc[mt][nt][0], acc[mt][nt][1]);
                    if (r + 8 < M)
                        *(__half2*)(C + (size_t)(r + 8) * ldc + c) =
                            __floats2half2_rn(acc[mt][nt][2], acc[mt][nt][3]);
                }
            }
    } else {
        float* C = (float*)Cv + (long long)blockIdx.z * sC;
        #pragma unroll
        for (int mt = 0; mt < 4; mt++)
            #pragma unroll
            for (int nt = 0; nt < 4; nt++) {
                const int r = row0 + warp_m * 64 + mt * 16 + lg;
                const int c = col0 + warp_n * 32 + nt * 8 + 2 * lt;
                if (c + 1 < N) {
                    if (r < M)
                        *(float2*)(C + (size_t)r * ldc + c) =
                            make_float2(acc[mt][nt][0], acc[mt][nt][1]);
                    if (r + 8 < M)
                        *(float2*)(C + (size_t)(r + 8) * ldc + c) =
                            make_float2(acc[mt][nt][2], acc[mt][nt][3]);
                }
            }
    }
}

// ============================================================================
// hgemm2: 128x256 tile, warp tile 64x64, 1 CTA/SM. N must be multiple of 256.
// ============================================================================
#define STA_H (128 * 40)
#define STB_H (256 * 40)
#define HG2_SMEM (3 * (STA_H + STB_H) * 2)

__global__ void __launch_bounds__(256, 1) hgemm2(
    const __half* __restrict__ A, int lda, long long sA,
    const __half* __restrict__ B, int ldb, long long sB,
    void* __restrict__ Cv, int ldc, long long sC,
    int M, int N, int K, int flags)
{
    const int row0 = blockIdx.y * 128;
    const int col0 = blockIdx.x * 256;
    if ((flags & F_SKIP) && col0 > row0 + 127) return;
    A += (long long)blockIdx.z * sA;
    B += (long long)blockIdx.z * sB;

    extern __shared__ __half dsm[];
    const uint32_t baseA = smem_u32(dsm);                 // 3 stages x 128x40
    const uint32_t baseB = baseA + 3 * STA_H * 2;         // 3 stages x 256x40

    const int tid    = threadIdx.x;
    const int lane   = tid & 31;
    const int wid    = tid >> 5;
    const int warp_m = wid >> 2;              // 0..1  (64 rows)
    const int warp_n = wid & 3;               // 0..3  (64 cols)
    const int lg     = lane >> 2;
    const int lt     = lane & 3;
    const int lq     = lane >> 3;
    const int lr     = lane & 7;

    const int Keff = (flags & F_KCAUSAL) ? (row0 + 128) : K;
    const int nk   = Keff >> 5;

    float acc[4][8][4];
    #pragma unroll
    for (int i = 0; i < 4; i++)
        #pragma unroll
        for (int j = 0; j < 8; j++)
            #pragma unroll
            for (int e = 0; e < 4; e++) acc[i][j][e] = 0.f;

    load_tile128(A, lda, row0, M, 0, baseA, tid);
    load_tile256(B, ldb, col0, N, 0, baseB, tid);
    asm volatile("cp.async.commit_group;" ::: "memory");
    if (nk > 1) {
        load_tile128(A, lda, row0, M, 32, baseA + STA_H * 2, tid);
        load_tile256(B, ldb, col0, N, 32, baseB + STB_H * 2, tid);
        asm volatile("cp.async.commit_group;" ::: "memory");
    }

    int sidx = 0;
    for (int i = 0; i < nk; i++) {
        if (i + 1 < nk) {
            asm volatile("cp.async.wait_group 1;" ::: "memory");
        } else {
            asm volatile("cp.async.wait_group 0;" ::: "memory");
        }
        __syncthreads();
        if (i + 2 < nk) {
            const int s2 = (sidx + 2) % 3;
            load_tile128(A, lda, row0, M, (i + 2) * 32, baseA + s2 * STA_H * 2, tid);
            load_tile256(B, ldb, col0, N, (i + 2) * 32, baseB + s2 * STB_H * 2, tid);
            asm volatile("cp.async.commit_group;" ::: "memory");
        }

        const uint32_t sA_ = baseA + sidx * STA_H * 2;
        const uint32_t sB_ = baseB + sidx * STB_H * 2;

        #pragma unroll
        for (int kk = 0; kk < 32; kk += 16) {
            uint32_t af[4][4];
            #pragma unroll
            for (int mt = 0; mt < 4; mt++) {
                const int r = warp_m * 64 + mt * 16 + (lq & 1) * 8 + lr;
                LDSM_X4(af[mt][0], af[mt][1], af[mt][2], af[mt][3],
                        sA_ + (r * 40 + kk + (lq >> 1) * 8) * 2);
            }
            uint32_t bf[4][4];
            #pragma unroll
            for (int np = 0; np < 4; np++) {
                const int n = warp_n * 64 + np * 16 + (lq >> 1) * 8 + lr;
                LDSM_X4(bf[np][0], bf[np][1], bf[np][2], bf[np][3],
                        sB_ + (n * 40 + kk + (lq & 1) * 8) * 2);
            }
            #pragma unroll
            for (int mt = 0; mt < 4; mt++)
                #pragma unroll
                for (int nt = 0; nt < 8; nt++)
                    mma16816(acc[mt][nt], af[mt], &bf[nt >> 1][(nt & 1) * 2]);
        }
        sidx = (sidx + 1) % 3;
    }

    if (flags & F_HALFOUT) {
        __half* C = (__half*)Cv + (long long)blockIdx.z * sC;
        #pragma unroll
        for (int mt = 0; mt < 4; mt++)
            #pragma unroll
            for (int nt = 0; nt < 8; nt++) {
                const int r = row0 + warp_m * 64 + mt * 16 + lg;
                const int c = col0 + warp_n * 64 + nt * 8 + 2 * lt;
                if (c + 1 < N) {
                    if (r < M)
                        *(__half2*)(C + (size_t)r * ldc + c) =
                            __floats2half2_rn(acc[mt][nt][0], acc[mt][nt][1]);
                    if (r + 8 < M)
                        *(__half2*)(C + (size_t)(r + 8) * ldc + c) =
                            __floats2half2_rn(acc[mt][nt][2], acc[mt][nt][3]);
                }
            }
    } else {
        float* C = (float*)Cv + (long long)blockIdx.z * sC;
        #pragma unroll
        for (int mt = 0; mt < 4; mt++)
            #pragma unroll
            for (int nt = 0; nt < 8; nt++) {
                const int r = row0 + warp_m * 64 + mt * 16 + lg;
                const int c = col0 + warp_n * 64 + nt * 8 + 2 * lt;
                if (c + 1 < N) {
                    if (r < M)
                        *(float2*)(C + (size_t)r * ldc + c) =
                            make_float2(acc[mt][nt][0], acc[mt][nt][1]);
                    if (r + 8 < M)
                        *(float2*)(C + (size_t)(r + 8) * ldc + c) =
                            make_float2(acc[mt][nt][2], acc[mt][nt][3]);
                }
            }
    }
}

// ---------------- f32 -> f16 convert ----------------
__global__ void cvt_f2h(const float* __restrict__ src, __half* __restrict__ dst, int n)
{
    int i = (blockIdx.x * blockDim.x + threadIdx.x) * 4;
    if (i < n) {
        float4 v = *(const float4*)(src + i);
        *(__half2*)(dst + i)     = __floats2half2_rn(v.x, v.y);
        *(__half2*)(dst + i + 2) = __floats2half2_rn(v.z, v.w);
    }
}

// ---------------- transpose f32 -> f16: dst[c][r] = src[r][c] ----------------
__global__ void transpose_kh(const float* __restrict__ src, int ld_src,
                             __half* __restrict__ dst, int R, int Cc)
{
    __shared__ float t[32][33];
    const int c0 = blockIdx.x * 32, r0 = blockIdx.y * 32;
    const int x = threadIdx.x, y = threadIdx.y;
    #pragma unroll
    for (int j = 0; j < 32; j += 8) {
        int r = r0 + y + j, c = c0 + x;
        t[y + j][x] = (r < R && c < Cc) ? src[(size_t)r * ld_src + c] : 0.f;
    }
    __syncthreads();
    #pragma unroll
    for (int j = 0; j < 32; j += 8) {
        int c = c0 + y + j, r = r0 + x;
        if (c < Cc && r < R) dst[(size_t)c * R + r] = __float2half(t[x][y + j]);
    }
}

// ---------------- w_uv -> [h][d][r] f16 ----------------
__global__ void transpose_wuv_h(const float* __restrict__ wuv)
{
    int idx = blockIdx.x * blockDim.x + threadIdx.x;
    if (idx < KV_LORA * NHEAD * D_V) {
        int r = idx >> 12;
        int h = (idx >> 7) & 31;
        int d = idx & 127;
        h_wuvT[((size_t)(h * 128 + d)) * KV_LORA + r] = __float2half(wuv[idx]);
    }
}

// ---------------- reductions ----------------
__device__ __forceinline__ float block_reduce_sum(float v, float* red)
{
    __syncthreads();
    const int lane = threadIdx.x & 31, wid = threadIdx.x >> 5;
    #pragma unroll
    for (int o = 16; o > 0; o >>= 1) v += __shfl_xor_sync(0xffffffffu, v, o);
    if (lane == 0) red[wid] = v;
    __syncthreads();
    const int nw = blockDim.x >> 5;
    float s = (threadIdx.x < nw) ? red[threadIdx.x] : 0.f;
    if (wid == 0) {
        #pragma unroll
        for (int o = 16; o > 0; o >>= 1) s += __shfl_xor_sync(0xffffffffu, s, o);
        if (lane == 0) red[0] = s;
    }
    __syncthreads();
    return red[0];
}

__device__ __forceinline__ float block_reduce_max(float v, float* red)
{
    __syncthreads();
    const int lane = threadIdx.x & 31, wid = threadIdx.x >> 5;
    #pragma unroll
    for (int o = 16; o > 0; o >>= 1) v = fmaxf(v, __shfl_xor_sync(0xffffffffu, v, o));
    if (lane == 0) red[wid] = v;
    __syncthreads();
    const int nw = blockDim.x >> 5;
    float s = (threadIdx.x < nw) ? red[threadIdx.x] : -3.0e38f;
    if (wid == 0) {
        #pragma unroll
        for (int o = 16; o > 0; o >>= 1) s = fmaxf(s, __shfl_xor_sync(0xffffffffu, s, o));
        if (lane == 0) red[0] = s;
    }
    __syncthreads();
    return red[0];
}

// ---------------- softmax: f16 scores -> f16 probs IN PLACE, one exp per element ----------------
__global__ void softmax_kernel()
{
    __shared__ float red[32];
    __shared__ float buf[T_SEQ];
    const int t = blockIdx.x;
    const int h = blockIdx.y;
    __half* row = h_probs + ((size_t)h * T_SEQ + t) * T_SEQ;
    const int n = t + 1;
    const float scale = rsqrtf(192.0f);

    float m = -3.0e38f;
    for (int i = threadIdx.x; i < n; i += blockDim.x) {
        float v = __half2float(row[i]) * scale;
        buf[i] = v;
        m = fmaxf(m, v);
    }
    m = block_reduce_max(m, red);

    float l = 0.f;
    for (int i = threadIdx.x; i < n; i += blockDim.x) {
        float e = __expf(buf[i] - m);
        buf[i] = e;
        l += e;
    }
    l = block_reduce_sum(l, red);
    const float inv = 1.0f / l;

    const int kblk = ((t >> 7) + 1) << 7;
    for (int i = threadIdx.x; i < kblk; i += blockDim.x)
        row[i] = __float2half((i < n) ? buf[i] * inv : 0.f);
}

// ---------------- rmsnorm: f32 in -> f16 out ----------------
__global__ void rmsnorm_h(const float* __restrict__ x, const float* __restrict__ scale,
                          __half* __restrict__ out, int N)
{
    __shared__ float red[32];
    const float* xr = x + (size_t)blockIdx.x * N;
    __half* orow = out + (size_t)blockIdx.x * N;
    float ss = 0.f;
    for (int i = threadIdx.x; i < N; i += blockDim.x) { float v = xr[i]; ss += v * v; }
    float tot = block_reduce_sum(ss, red);
    float r = rsqrtf(tot / (float)N + EPS_RMS);
    for (int i = threadIdx.x; i < N; i += blockDim.x)
        orow[i] = __float2half(xr[i] * r * scale[i]);
}

// ---------------- kv post: rmsnorm -> caug[:,0:512]; rope -> caug[:,512:576] (f32) ----------------
__global__ void kv_post_kernel(const int* __restrict__ pos, const float* __restrict__ scale)
{
    __shared__ float red[32];
    const int t = blockIdx.x;
    const float* row = g_kva + (size_t)t * D_AUG;
    float* crow = g_caug + (size_t)t * D_AUG;
    float ss = 0.f;
    for (int i = threadIdx.x; i < KV_LORA; i += blockDim.x) { float v = row[i]; ss += v * v; }
    float tot = block_reduce_sum(ss, red);
    float r = rsqrtf(tot / (float)KV_LORA + EPS_RMS);
    for (int i = threadIdx.x; i < KV_LORA; i += blockDim.x)
        crow[i] = row[i] * r * scale[i];
    if (threadIdx.x < D_ROPE / 2) {
        int i = threadIdx.x;
        float p = (float)pos[t];
        float inv = __powf(10000.0f, -(float)i * (1.0f / 32.0f));
        float ang = p * inv;
        float c = cosf(ang), s = sinf(ang);
        float x1 = row[KV_LORA + 2*i], x2 = row[KV_LORA + 2*i + 1];
        crow[KV_LORA + 2*i    ] = x1 * c - x2 * s;
        crow[KV_LORA + 2*i + 1] = x1 * s + x2 * c;
    }
}

// ---------------- fused q rope + f16 convert ----------------
__global__ void q_rope_cvt(const int* __restrict__ pos)
{
    const int t = blockIdx.x;
    const float p = (float)pos[t];
    const float* src = g_q + (size_t)t * (NHEAD * D_QK);
    __half* dst = h_q + (size_t)t * (NHEAD * D_QK);
    for (int idx = threadIdx.x; idx < NHEAD * D_QK / 2; idx += blockDim.x) {
        const int c = idx * 2;
        const int o = c % D_QK;
        float x1 = src[c], x2 = src[c + 1];
        if (o >= D_NOPE) {
            const int j = (o - D_NOPE) >> 1;
            float inv = __powf(10000.0f, -(float)j * (1.0f / 32.0f));
            float ang = p * inv;
            float cc = cosf(ang), ss = sinf(ang);
            float y1 = x1 * cc - x2 * ss;
            float y2 = x1 * ss + x2 * cc;
            x1 = y1; x2 = y2;
        }
        *(__half2*)(dst + c) = __floats2half2_rn(x1, x2);
    }
}

// ---------------- copy roped q into h_qaug[:, 512:576] ----------------
__global__ void qaug_rope_kernel()
{
    const int t = blockIdx.x;
    for (int idx = threadIdx.x; idx < NHEAD * D_ROPE; idx += blockDim.x) {
        int h = idx >> 6, k = idx & 63;
        h_qaug[((size_t)h * T_SEQ + t) * D_AUG + KV_LORA + k] =
            h_q[(size_t)t * (NHEAD * D_QK) + h * D_QK + D_NOPE + k];
    }
}

// ---------------- host launcher ----------------
extern "C" void kernel_launch(void* const* d_in, const int* in_sizes, int n_in,
                              void* d_out, int out_size)
{
    const float* hs     = (const float*)d_in[0];
    const int*   pos    = (const int*)  d_in[1];
    const float* w_qa   = (const float*)d_in[2];
    const float* qa_ln  = (const float*)d_in[3];
    const float* w_qb   = (const float*)d_in[4];
    const float* w_kva  = (const float*)d_in[5];
    const float* kva_ln = (const float*)d_in[6];
    const float* w_uk   = (const float*)d_in[7];
    const float* w_uv   = (const float*)d_in[8];
    const float* w_o    = (const float*)d_in[9];
    float* out = (float*)d_out;

    float  *p_qc, *p_q, *p_kva, *p_caug;
    __half *p_hs, *p_hqc, *p_hq, *p_hwuk, *p_hqaug, *p_hcaug, *p_hcompT,
           *p_hprobs, *p_hol, *p_hov, *p_wqaT, *p_wqbT, *p_wkvaT, *p_woT, *p_wuvT;
    cudaGetSymbolAddress((void**)&p_qc,     g_qc);
    cudaGetSymbolAddress((void**)&p_q,      g_q);
    cudaGetSymbolAddress((void**)&p_kva,    g_kva);
    cudaGetSymbolAddress((void**)&p_caug,   g_caug);
    cudaGetSymbolAddress((void**)&p_hs,     h_hs);
    cudaGetSymbolAddress((void**)&p_hqc,    h_qc);
    cudaGetSymbolAddress((void**)&p_hq,     h_q);
    cudaGetSymbolAddress((void**)&p_hwuk,   h_wuk);
    cudaGetSymbolAddress((void**)&p_hqaug,  h_qaug);
    cudaGetSymbolAddress((void**)&p_hcaug,  h_caug);
    cudaGetSymbolAddress((void**)&p_hcompT, h_compT);
    cudaGetSymbolAddress((void**)&p_hprobs, h_probs);
    cudaGetSymbolAddress((void**)&p_hol,    h_ol);
    cudaGetSymbolAddress((void**)&p_hov,    h_ov);
    cudaGetSymbolAddress((void**)&p_wqaT,   h_wqaT);
    cudaGetSymbolAddress((void**)&p_wqbT,   h_wqbT);
    cudaGetSymbolAddress((void**)&p_wkvaT,  h_wkvaT);
    cudaGetSymbolAddress((void**)&p_woT,    h_woT);
    cudaGetSymbolAddress((void**)&p_wuvT,   h_wuvT);

    cudaFuncSetAttribute(hgemm,  cudaFuncAttributeMaxDynamicSharedMemorySize, HG_SMEM);
    cudaFuncSetAttribute(hgemm2, cudaFuncAttributeMaxDynamicSharedMemorySize, HG2_SMEM);

    dim3 tb(32, 8);
    // operand prep
    cvt_f2h<<<(T_SEQ*HID/4 + 255)/256, 256>>>(hs, p_hs, T_SEQ*HID);
    transpose_kh<<<dim3(Q_LORA/32, HID/32), tb>>>(w_qa, Q_LORA, p_wqaT, HID, Q_LORA);
    transpose_kh<<<dim3((NHEAD*D_QK)/32, Q_LORA/32), tb>>>(w_qb, NHEAD*D_QK, p_wqbT, Q_LORA, NHEAD*D_QK);
    transpose_kh<<<dim3(D_AUG/32, HID/32), tb>>>(w_kva, D_AUG, p_wkvaT, HID, D_AUG);
    transpose_kh<<<dim3(HID/32, HID/32), tb>>>(w_o, HID, p_woT, HID, HID);
    cvt_f2h<<<(KV_LORA*NHEAD*D_NOPE/4 + 255)/256, 256>>>(w_uk, p_hwuk, KV_LORA*NHEAD*D_NOPE);
    transpose_wuv_h<<<(KV_LORA*NHEAD*D_V + 255)/256, 256>>>(w_uv);

    // q_c = rmsnorm(hs @ w_qa) -> f16
    hgemm2<<<dim3(Q_LORA/256, T_SEQ/128, 1), 256, HG2_SMEM>>>(
        p_hs, HID, 0, p_wqaT, HID, 0, p_qc, Q_LORA, 0, T_SEQ, Q_LORA, HID, 0);
    rmsnorm_h<<<T_SEQ, 256>>>(p_qc, qa_ln, p_hqc, Q_LORA);

    // q = q_c @ w_qb (f32), fused rope + convert -> h_q
    hgemm2<<<dim3((NHEAD*D_QK)/256, T_SEQ/128, 1), 256, HG2_SMEM>>>(
        p_hqc, Q_LORA, 0, p_wqbT, Q_LORA, 0, p_q, NHEAD*D_QK, 0,
        T_SEQ, NHEAD*D_QK, Q_LORA, 0);
    q_rope_cvt<<<T_SEQ, 256>>>(pos);

    // qaug[h][:,0:512] = q_nope[:,h,:] @ w_uk[:,h,:]^T  -> f16
    hgemm2<<<dim3(KV_LORA/256, T_SEQ/128, NHEAD), 256, HG2_SMEM>>>(
        p_hq, NHEAD*D_QK, (long long)D_QK,
        p_hwuk, NHEAD*D_NOPE, (long long)D_NOPE,
        p_hqaug, D_AUG, (long long)T_SEQ*D_AUG,
        T_SEQ, KV_LORA, D_NOPE, F_HALFOUT);
    qaug_rope_kernel<<<T_SEQ, 256>>>();

    // kv_a = hs @ w_kva (f32; N=576 -> fallback kernel), then rmsnorm+rope
    hgemm<<<dim3((D_AUG+127)/128, T_SEQ/128, 1), 256, HG_SMEM>>>(
        p_hs, HID, 0, p_wkvaT, HID, 0, p_kva, D_AUG, 0, T_SEQ, D_AUG, HID, 0);
    kv_post_kernel<<<T_SEQ, 256>>>(pos, kva_ln);
    cvt_f2h<<<(T_SEQ*D_AUG/4 + 255)/256, 256>>>(p_caug, p_hcaug, T_SEQ*D_AUG);
    transpose_kh<<<dim3(KV_LORA/32, T_SEQ/32), tb>>>(p_caug, D_AUG, p_hcompT, T_SEQ, KV_LORA);

    // scores[h] = Qaug[h] @ Caug^T  -> f16 directly into h_probs (causal skip)
    hgemm2<<<dim3(T_SEQ/256, T_SEQ/128, NHEAD), 256, HG2_SMEM>>>(
        p_hqaug, D_AUG, (long long)T_SEQ*D_AUG,
        p_hcaug, D_AUG, 0,
        p_hprobs, T_SEQ, (long long)T_SEQ*T_SEQ,
        T_SEQ, T_SEQ, D_AUG, F_SKIP | F_HALFOUT);

    // softmax in place on h_probs
    softmax_kernel<<<dim3(T_SEQ, NHEAD), 256>>>();

    // O[h] = P[h] @ comp  -> f16 (K capped at row0+128)
    hgemm2<<<dim3(KV_LORA/256, T_SEQ/128, NHEAD), 256, HG2_SMEM>>>(
        p_hprobs, T_SEQ, (long long)T_SEQ*T_SEQ,
        p_hcompT, T_SEQ, 0,
        p_hol, KV_LORA, (long long)T_SEQ*KV_LORA,
        T_SEQ, KV_LORA, T_SEQ, F_KCAUSAL | F_HALFOUT);

    // o_v[:, h*128:(h+1)*128] = O[h] @ w_uv[:,h,:]  -> f16 (N=128 -> fallback)
    hgemm<<<dim3(1, T_SEQ/128, NHEAD), 256, HG_SMEM>>>(
        p_hol, KV_LORA, (long long)T_SEQ*KV_LORA,
        p_wuvT, KV_LORA, (long long)D_V*KV_LORA,
        p_hov, NHEAD*D_V, (long long)D_V,
        T_SEQ, D_V, KV_LORA, F_HALFOUT);

    // out = o_v @ w_o (f32)
    hgemm2<<<dim3(HID/256, T_SEQ/128, 1), 256, HG2_SMEM>>>(
        p_hov, NHEAD*D_V, 0, p_woT, NHEAD*D_V, 0, out, HID, 0,
        T_SEQ, HID, NHEAD*D_V, 0);
}

// round 12
// speedup vs baseline: 1.1206x; 1.1206x over previous
#include <cuda_runtime.h>
#include <cuda_fp16.h>
#include <math.h>
#include <stdint.h>

#define T_SEQ   2048
#define HID     4096
#define NHEAD   32
#define Q_LORA  1536
#define KV_LORA 512
#define D_NOPE  128
#define D_ROPE  64
#define D_QK    192
#define D_V     128
#define D_AUG   576
#define EPS_RMS 1e-6f

#define F_KCAUSAL 1   // K_eff = row0 + 128 (PV with zero-padded P)
#define F_SKIP    4   // skip blocks fully above causal diagonal
#define F_HALFOUT 8   // C is __half*

// ---------------- scratch (device globals) ----------------
__device__ float  g_qc    [T_SEQ * Q_LORA];
__device__ float  g_q     [T_SEQ * NHEAD * D_QK];
__device__ float  g_kva   [T_SEQ * D_AUG];
__device__ float  g_caug  [T_SEQ * D_AUG];

__device__ __half h_hs    [T_SEQ * HID];
__device__ __half h_qc    [T_SEQ * Q_LORA];
__device__ __half h_q     [T_SEQ * NHEAD * D_QK];
__device__ __half h_wuk   [KV_LORA * NHEAD * D_NOPE];            // [r][h][d]
__device__ __half h_qaug  [(size_t)NHEAD * T_SEQ * D_AUG];       // [h][t][576]
__device__ __half h_caug  [T_SEQ * D_AUG];                       // [s][576]
__device__ __half h_compT [KV_LORA * T_SEQ];                     // [r][s]
__device__ __half h_probs [(size_t)NHEAD * T_SEQ * T_SEQ];       // [h][t][s] scores->probs in place
__device__ __half h_ol    [(size_t)NHEAD * T_SEQ * KV_LORA];     // [h][t][r]
__device__ __half h_ov    [T_SEQ * NHEAD * D_V];
__device__ __half h_wqaT  [Q_LORA * HID];
__device__ __half h_wqbT  [(NHEAD*D_QK) * Q_LORA];
__device__ __half h_wkvaT [D_AUG * HID];
__device__ __half h_woT   [HID * HID];
__device__ __half h_wuvT  [NHEAD * D_V * KV_LORA];               // [h][d][r]

// ---------------- helpers ----------------
__device__ __forceinline__ uint32_t smem_u32(const void* p)
{
    uint32_t a;
    asm("{ .reg .u64 t; cvta.to.shared.u64 t, %1; cvt.u32.u64 %0, t; }" : "=r"(a) : "l"(p));
    return a;
}

__device__ __forceinline__ void mma16816(float c[4], const uint32_t a[4], const uint32_t b[2])
{
    asm volatile(
        "mma.sync.aligned.m16n8k16.row.col.f32.f16.f16.f32 "
        "{%0,%1,%2,%3}, {%4,%5,%6,%7}, {%8,%9}, {%0,%1,%2,%3};"
        : "+f"(c[0]), "+f"(c[1]), "+f"(c[2]), "+f"(c[3])
        : "r"(a[0]), "r"(a[1]), "r"(a[2]), "r"(a[3]), "r"(b[0]), "r"(b[1]));
}

#define LDSM_X4(r0, r1, r2, r3, addr) \
    asm volatile("ldmatrix.sync.aligned.m8n8.x4.shared.b16 {%0,%1,%2,%3}, [%4];" \
        : "=r"(r0), "=r"(r1), "=r"(r2), "=r"(r3) : "r"(addr))

__device__ __forceinline__ void cpa16(uint32_t dst, const void* src, int sz)
{
    asm volatile("cp.async.cg.shared.global [%0], [%1], 16, %2;"
        :: "r"(dst), "l"(src), "r"(sz) : "memory");
}

// load [128 rows][64 halves] tile into smem (row stride 72 halves = 144B)
// 256 threads: 2 threads per row, 64B each
__device__ __forceinline__ void load_tile64(
    const __half* __restrict__ src, int ld, int r0, int nvalid, int k0,
    uint32_t dst, int tid)
{
    const int row = tid >> 1;
    const int half32 = (tid & 1);                 // 0 or 1: which 32-half block
    const __half* g = src + (size_t)(r0 + row) * ld + k0 + half32 * 32;
    const uint32_t d = dst + row * 144 + half32 * 64;
    const int sz = ((r0 + row) < nvalid) ? 16 : 0;
    cpa16(d,      g,      sz);
    cpa16(d + 16, g + 8,  sz);
    cpa16(d + 32, g + 16, sz);
    cpa16(d + 48, g + 24, sz);
}

// ============================================================================
// hgemm: 128x128 tile, BK=64, 2-stage cp.async pipeline.
// Correct ordering: wait_group 0 -> __syncthreads -> issue next loads -> compute.
// ============================================================================
#define STAGE_H (128 * 72)            // halves per operand per stage
#define HG_SMEM (2 * STAGE_H * 2 * 2) // bytes total (A+B, 2 stages) = 73728

__global__ void __launch_bounds__(256, 2) hgemm(
    const __half* __restrict__ A, int lda, long long sA,
    const __half* __restrict__ B, int ldb, long long sB,
    void* __restrict__ Cv, int ldc, long long sC,
    int M, int N, int K, int flags)
{
    const int row0 = blockIdx.y * 128;
    const int col0 = blockIdx.x * 128;
    if ((flags & F_SKIP) && col0 > row0 + 127) return;
    A += (long long)blockIdx.z * sA;
    B += (long long)blockIdx.z * sB;

    extern __shared__ __half dsm[];
    const uint32_t baseA = smem_u32(dsm);
    const uint32_t baseB = baseA + 2 * STAGE_H * 2;

    const int tid    = threadIdx.x;
    const int lane   = tid & 31;
    const int wid    = tid >> 5;
    const int warp_m = wid >> 2;
    const int warp_n = wid & 3;
    const int lg     = lane >> 2;
    const int lt     = lane & 3;
    const int lq     = lane >> 3;
    const int lr     = lane & 7;

    const int Keff = (flags & F_KCAUSAL) ? (row0 + 128) : K;
    const int nk   = Keff >> 6;                   // k64 tiles

    float acc[4][4][4];
    #pragma unroll
    for (int i = 0; i < 4; i++)
        #pragma unroll
        for (int j = 0; j < 4; j++)
            #pragma unroll
            for (int e = 0; e < 4; e++) acc[i][j][e] = 0.f;

    // preload tile 0 into stage 0
    load_tile64(A, lda, row0, M, 0, baseA, tid);
    load_tile64(B, ldb, col0, N, 0, baseB, tid);
    asm volatile("cp.async.commit_group;" ::: "memory");

    for (int i = 0; i < nk; i++) {
        const int b = i & 1;
        // my tile-i copies complete...
        asm volatile("cp.async.wait_group 0;" ::: "memory");
        // ...and everyone's (barrier also proves compute(i-1) done -> stage 1-b free)
        __syncthreads();
        if (i + 1 < nk) {
            load_tile64(A, lda, row0, M, (i + 1) * 64, baseA + (1 - b) * STAGE_H * 2, tid);
            load_tile64(B, ldb, col0, N, (i + 1) * 64, baseB + (1 - b) * STAGE_H * 2, tid);
            asm volatile("cp.async.commit_group;" ::: "memory");
        }

        const uint32_t sA_ = baseA + b * STAGE_H * 2;
        const uint32_t sB_ = baseB + b * STAGE_H * 2;

        #pragma unroll
        for (int kk = 0; kk < 64; kk += 16) {
            uint32_t af[4][4];
            #pragma unroll
            for (int mt = 0; mt < 4; mt++) {
                const int r = warp_m * 64 + mt * 16 + (lq & 1) * 8 + lr;
                LDSM_X4(af[mt][0], af[mt][1], af[mt][2], af[mt][3],
                        sA_ + (r * 72 + kk + (lq >> 1) * 8) * 2);
            }
            uint32_t bf[2][4];
            #pragma unroll
            for (int np = 0; np < 2; np++) {
                const int n = warp_n * 32 + np * 16 + (lq >> 1) * 8 + lr;
                LDSM_X4(bf[np][0], bf[np][1], bf[np][2], bf[np][3],
                        sB_ + (n * 72 + kk + (lq & 1) * 8) * 2);
            }
            #pragma unroll
            for (int mt = 0; mt < 4; mt++)
                #pragma unroll
                for (int nt = 0; nt < 4; nt++)
                    mma16816(acc[mt][nt], af[mt], &bf[nt >> 1][(nt & 1) * 2]);
        }
    }

    // ---- epilogue ----
    if (flags & F_HALFOUT) {
        __half* C = (__half*)Cv + (long long)blockIdx.z * sC;
        #pragma unroll
        for (int mt = 0; mt < 4; mt++)
            #pragma unroll
            for (int nt = 0; nt < 4; nt++) {
                const int r = row0 + warp_m * 64 + mt * 16 + lg;
                const int c = col0 + warp_n * 32 + nt * 8 + 2 * lt;
                if (c + 1 < N) {
                    if (r < M)
                        *(__half2*)(C + (size_t)r * ldc + c) =
                            __floats2half2_rn(acc[mt][nt][0], acc[mt][nt][1]);
                    if (r + 8 < M)
                        *(__half2*)(C + (size_t)(r + 8) * ldc + c) =
                            __floats2half2_rn(acc[mt][nt][2], acc[mt][nt][3]);
                }
            }
    } else {
        float* C = (float*)Cv + (long long)blockIdx.z * sC;
        #pragma unroll
        for (int mt = 0; mt < 4; mt++)
            #pragma unroll
            for (int nt = 0; nt < 4; nt++) {
                const int r = row0 + warp_m * 64 + mt * 16 + lg;
                const int c = col0 + warp_n * 32 + nt * 8 + 2 * lt;
                if (c + 1 < N) {
                    if (r < M)
                        *(float2*)(C + (size_t)r * ldc + c) =
                            make_float2(acc[mt][nt][0], acc[mt][nt][1]);
                    if (r + 8 < M)
                        *(float2*)(C + (size_t)(r + 8) * ldc + c) =
                            make_float2(acc[mt][nt][2], acc[mt][nt][3]);
                }
            }
    }
}

// ---------------- f32 -> f16 convert ----------------
__global__ void cvt_f2h(const float* __restrict__ src, __half* __restrict__ dst, int n)
{
    int i = (blockIdx.x * blockDim.x + threadIdx.x) * 4;
    if (i < n) {
        float4 v = *(const float4*)(src + i);
        *(__half2*)(dst + i)     = __floats2half2_rn(v.x, v.y);
        *(__half2*)(dst + i + 2) = __floats2half2_rn(v.z, v.w);
    }
}

// ---------------- transpose f32 -> f16: dst[c][r] = src[r][c] ----------------
__global__ void transpose_kh(const float* __restrict__ src, int ld_src,
                             __half* __restrict__ dst, int R, int Cc)
{
    __shared__ float t[32][33];
    const int c0 = blockIdx.x * 32, r0 = blockIdx.y * 32;
    const int x = threadIdx.x, y = threadIdx.y;
    #pragma unroll
    for (int j = 0; j < 32; j += 8) {
        int r = r0 + y + j, c = c0 + x;
        t[y + j][x] = (r < R && c < Cc) ? src[(size_t)r * ld_src + c] : 0.f;
    }
    __syncthreads();
    #pragma unroll
    for (int j = 0; j < 32; j += 8) {
        int c = c0 + y + j, r = r0 + x;
        if (c < Cc && r < R) dst[(size_t)c * R + r] = __float2half(t[x][y + j]);
    }
}

// ---------------- w_uv -> [h][d][r] f16 ----------------
__global__ void transpose_wuv_h(const float* __restrict__ wuv)
{
    int idx = blockIdx.x * blockDim.x + threadIdx.x;
    if (idx < KV_LORA * NHEAD * D_V) {
        int r = idx >> 12;
        int h = (idx >> 7) & 31;
        int d = idx & 127;
        h_wuvT[((size_t)(h * 128 + d)) * KV_LORA + r] = __float2half(wuv[idx]);
    }
}

// ---------------- reductions ----------------
__device__ __forceinline__ float block_reduce_sum(float v, float* red)
{
    __syncthreads();
    const int lane = threadIdx.x & 31, wid = threadIdx.x >> 5;
    #pragma unroll
    for (int o = 16; o > 0; o >>= 1) v += __shfl_xor_sync(0xffffffffu, v, o);
    if (lane == 0) red[wid] = v;
    __syncthreads();
    const int nw = blockDim.x >> 5;
    float s = (threadIdx.x < nw) ? red[threadIdx.x] : 0.f;
    if (wid == 0) {
        #pragma unroll
        for (int o = 16; o > 0; o >>= 1) s += __shfl_xor_sync(0xffffffffu, s, o);
        if (lane == 0) red[0] = s;
    }
    __syncthreads();
    return red[0];
}

__device__ __forceinline__ float block_reduce_max(float v, float* red)
{
    __syncthreads();
    const int lane = threadIdx.x & 31, wid = threadIdx.x >> 5;
    #pragma unroll
    for (int o = 16; o > 0; o >>= 1) v = fmaxf(v, __shfl_xor_sync(0xffffffffu, v, o));
    if (lane == 0) red[wid] = v;
    __syncthreads();
    const int nw = blockDim.x >> 5;
    float s = (threadIdx.x < nw) ? red[threadIdx.x] : -3.0e38f;
    if (wid == 0) {
        #pragma unroll
        for (int o = 16; o > 0; o >>= 1) s = fmaxf(s, __shfl_xor_sync(0xffffffffu, s, o));
        if (lane == 0) red[0] = s;
    }
    __syncthreads();
    return red[0];
}

// ---------------- softmax: f16 scores -> f16 probs IN PLACE, one exp per element ----------------
__global__ void softmax_kernel()
{
    __shared__ float red[32];
    __shared__ float buf[T_SEQ];
    const int t = blockIdx.x;
    const int h = blockIdx.y;
    __half* row = h_probs + ((size_t)h * T_SEQ + t) * T_SEQ;
    const int n = t + 1;
    const float scale = rsqrtf(192.0f);

    float m = -3.0e38f;
    for (int i = threadIdx.x; i < n; i += blockDim.x) {
        float v = __half2float(row[i]) * scale;
        buf[i] = v;
        m = fmaxf(m, v);
    }
    m = block_reduce_max(m, red);

    float l = 0.f;
    for (int i = threadIdx.x; i < n; i += blockDim.x) {
        float e = __expf(buf[i] - m);
        buf[i] = e;
        l += e;
    }
    l = block_reduce_sum(l, red);
    const float inv = 1.0f / l;

    const int kblk = ((t >> 7) + 1) << 7;
    for (int i = threadIdx.x; i < kblk; i += blockDim.x)
        row[i] = __float2half((i < n) ? buf[i] * inv : 0.f);
}

// ---------------- rmsnorm: f32 in -> f16 out ----------------
__global__ void rmsnorm_h(const float* __restrict__ x, const float* __restrict__ scale,
                          __half* __restrict__ out, int N)
{
    __shared__ float red[32];
    const float* xr = x + (size_t)blockIdx.x * N;
    __half* orow = out + (size_t)blockIdx.x * N;
    float ss = 0.f;
    for (int i = threadIdx.x; i < N; i += blockDim.x) { float v = xr[i]; ss += v * v; }
    float tot = block_reduce_sum(ss, red);
    float r = rsqrtf(tot / (float)N + EPS_RMS);
    for (int i = threadIdx.x; i < N; i += blockDim.x)
        orow[i] = __float2half(xr[i] * r * scale[i]);
}

// ---------------- kv post: rmsnorm -> caug[:,0:512]; rope -> caug[:,512:576] (f32) ----------------
__global__ void kv_post_kernel(const int* __restrict__ pos, const float* __restrict__ scale)
{
    __shared__ float red[32];
    const int t = blockIdx.x;
    const float* row = g_kva + (size_t)t * D_AUG;
    float* crow = g_caug + (size_t)t * D_AUG;
    float ss = 0.f;
    for (int i = threadIdx.x; i < KV_LORA; i += blockDim.x) { float v = row[i]; ss += v * v; }
    float tot = block_reduce_sum(ss, red);
    float r = rsqrtf(tot / (float)KV_LORA + EPS_RMS);
    for (int i = threadIdx.x; i < KV_LORA; i += blockDim.x)
        crow[i] = row[i] * r * scale[i];
    if (threadIdx.x < D_ROPE / 2) {
        int i = threadIdx.x;
        float p = (float)pos[t];
        float inv = __powf(10000.0f, -(float)i * (1.0f / 32.0f));
        float ang = p * inv;
        float c = cosf(ang), s = sinf(ang);
        float x1 = row[KV_LORA + 2*i], x2 = row[KV_LORA + 2*i + 1];
        crow[KV_LORA + 2*i    ] = x1 * c - x2 * s;
        crow[KV_LORA + 2*i + 1] = x1 * s + x2 * c;
    }
}

// ---------------- fused q rope + f16 convert ----------------
__global__ void q_rope_cvt(const int* __restrict__ pos)
{
    const int t = blockIdx.x;
    const float p = (float)pos[t];
    const float* src = g_q + (size_t)t * (NHEAD * D_QK);
    __half* dst = h_q + (size_t)t * (NHEAD * D_QK);
    for (int idx = threadIdx.x; idx < NHEAD * D_QK / 2; idx += blockDim.x) {
        const int c = idx * 2;
        const int o = c % D_QK;
        float x1 = src[c], x2 = src[c + 1];
        if (o >= D_NOPE) {
            const int j = (o - D_NOPE) >> 1;
            float inv = __powf(10000.0f, -(float)j * (1.0f / 32.0f));
            float ang = p * inv;
            float cc = cosf(ang), ss = sinf(ang);
            float y1 = x1 * cc - x2 * ss;
            float y2 = x1 * ss + x2 * cc;
            x1 = y1; x2 = y2;
        }
        *(__half2*)(dst + c) = __floats2half2_rn(x1, x2);
    }
}

// ---------------- copy roped q into h_qaug[:, 512:576] ----------------
__global__ void qaug_rope_kernel()
{
    const int t = blockIdx.x;
    for (int idx = threadIdx.x; idx < NHEAD * D_ROPE; idx += blockDim.x) {
        int h = idx >> 6, k = idx & 63;
        h_qaug[((size_t)h * T_SEQ + t) * D_AUG + KV_LORA + k] =
            h_q[(size_t)t * (NHEAD * D_QK) + h * D_QK + D_NOPE + k];
    }
}

// ---------------- host launcher ----------------
extern "C" void kernel_launch(void* const* d_in, const int* in_sizes, int n_in,
                              void* d_out, int out_size)
{
    const float* hs     = (const float*)d_in[0];
    const int*   pos    = (const int*)  d_in[1];
    const float* w_qa   = (const float*)d_in[2];
    const float* qa_ln  = (const float*)d_in[3];
    const float* w_qb   = (const float*)d_in[4];
    const float* w_kva  = (const float*)d_in[5];
    const float* kva_ln = (const float*)d_in[6];
    const float* w_uk   = (const float*)d_in[7];
    const float* w_uv   = (const float*)d_in[8];
    const float* w_o    = (const float*)d_in[9];
    float* out = (float*)d_out;

    float  *p_qc, *p_q, *p_kva, *p_caug;
    __half *p_hs, *p_hqc, *p_hq, *p_hwuk, *p_hqaug, *p_hcaug, *p_hcompT,
           *p_hprobs, *p_hol, *p_hov, *p_wqaT, *p_wqbT, *p_wkvaT, *p_woT, *p_wuvT;
    cudaGetSymbolAddress((void**)&p_qc,     g_qc);
    cudaGetSymbolAddress((void**)&p_q,      g_q);
    cudaGetSymbolAddress((void**)&p_kva,    g_kva);
    cudaGetSymbolAddress((void**)&p_caug,   g_caug);
    cudaGetSymbolAddress((void**)&p_hs,     h_hs);
    cudaGetSymbolAddress((void**)&p_hqc,    h_qc);
    cudaGetSymbolAddress((void**)&p_hq,     h_q);
    cudaGetSymbolAddress((void**)&p_hwuk,   h_wuk);
    cudaGetSymbolAddress((void**)&p_hqaug,  h_qaug);
    cudaGetSymbolAddress((void**)&p_hcaug,  h_caug);
    cudaGetSymbolAddress((void**)&p_hcompT, h_compT);
    cudaGetSymbolAddress((void**)&p_hprobs, h_probs);
    cudaGetSymbolAddress((void**)&p_hol,    h_ol);
    cudaGetSymbolAddress((void**)&p_hov,    h_ov);
    cudaGetSymbolAddress((void**)&p_wqaT,   h_wqaT);
    cudaGetSymbolAddress((void**)&p_wqbT,   h_wqbT);
    cudaGetSymbolAddress((void**)&p_wkvaT,  h_wkvaT);
    cudaGetSymbolAddress((void**)&p_woT,    h_woT);
    cudaGetSymbolAddress((void**)&p_wuvT,   h_wuvT);

    cudaFuncSetAttribute(hgemm, cudaFuncAttributeMaxDynamicSharedMemorySize, HG_SMEM);

    dim3 tb(32, 8);
    // operand prep
    cvt_f2h<<<(T_SEQ*HID/4 + 255)/256, 256>>>(hs, p_hs, T_SEQ*HID);
    transpose_kh<<<dim3(Q_LORA/32, HID/32), tb>>>(w_qa, Q_LORA, p_wqaT, HID, Q_LORA);
    transpose_kh<<<dim3((NHEAD*D_QK)/32, Q_LORA/32), tb>>>(w_qb, NHEAD*D_QK, p_wqbT, Q_LORA, NHEAD*D_QK);
    transpose_kh<<<dim3(D_AUG/32, HID/32), tb>>>(w_kva, D_AUG, p_wkvaT, HID, D_AUG);
    transpose_kh<<<dim3(HID/32, HID/32), tb>>>(w_o, HID, p_woT, HID, HID);
    cvt_f2h<<<(KV_LORA*NHEAD*D_NOPE/4 + 255)/256, 256>>>(w_uk, p_hwuk, KV_LORA*NHEAD*D_NOPE);
    transpose_wuv_h<<<(KV_LORA*NHEAD*D_V + 255)/256, 256>>>(w_uv);

    // q_c = rmsnorm(hs @ w_qa) -> f16
    hgemm<<<dim3(Q_LORA/128, T_SEQ/128, 1), 256, HG_SMEM>>>(
        p_hs, HID, 0, p_wqaT, HID, 0, p_qc, Q_LORA, 0, T_SEQ, Q_LORA, HID, 0);
    rmsnorm_h<<<T_SEQ, 256>>>(p_qc, qa_ln, p_hqc, Q_LORA);

    // q = q_c @ w_qb (f32), fused rope + convert -> h_q
    hgemm<<<dim3((NHEAD*D_QK)/128, T_SEQ/128, 1), 256, HG_SMEM>>>(
        p_hqc, Q_LORA, 0, p_wqbT, Q_LORA, 0, p_q, NHEAD*D_QK, 0,
        T_SEQ, NHEAD*D_QK, Q_LORA, 0);
    q_rope_cvt<<<T_SEQ, 256>>>(pos);

    // qaug[h][:,0:512] = q_nope[:,h,:] @ w_uk[:,h,:]^T  -> f16
    hgemm<<<dim3(KV_LORA/128, T_SEQ/128, NHEAD), 256, HG_SMEM>>>(
        p_hq, NHEAD*D_QK, (long long)D_QK,
        p_hwuk, NHEAD*D_NOPE, (long long)D_NOPE,
        p_hqaug, D_AUG, (long long)T_SEQ*D_AUG,
        T_SEQ, KV_LORA, D_NOPE, F_HALFOUT);
    qaug_rope_kernel<<<T_SEQ, 256>>>();

    // kv_a = hs @ w_kva (f32), then rmsnorm+rope -> caug f32 -> f16 (+transposed)
    hgemm<<<dim3((D_AUG+127)/128, T_SEQ/128, 1), 256, HG_SMEM>>>(
        p_hs, HID, 0, p_wkvaT, HID, 0, p_kva, D_AUG, 0, T_SEQ, D_AUG, HID, 0);
    kv_post_kernel<<<T_SEQ, 256>>>(pos, kva_ln);
    cvt_f2h<<<(T_SEQ*D_AUG/4 + 255)/256, 256>>>(p_caug, p_hcaug, T_SEQ*D_AUG);
    transpose_kh<<<dim3(KV_LORA/32, T_SEQ/32), tb>>>(p_caug, D_AUG, p_hcompT, T_SEQ, KV_LORA);

    // scores[h] = Qaug[h] @ Caug^T -> f16 directly into h_probs (causal skip)
    hgemm<<<dim3(T_SEQ/128, T_SEQ/128, NHEAD), 256, HG_SMEM>>>(
        p_hqaug, D_AUG, (long long)T_SEQ*D_AUG,
        p_hcaug, D_AUG, 0,
        p_hprobs, T_SEQ, (long long)T_SEQ*T_SEQ,
        T_SEQ, T_SEQ, D_AUG, F_SKIP | F_HALFOUT);

    // softmax in place on h_probs (zero-pads to 128 boundary)
    softmax_kernel<<<dim3(T_SEQ, NHEAD), 256>>>();

    // O[h] = P[h] @ comp  -> f16 (K capped at row0+128)
    hgemm<<<dim3(KV_LORA/128, T_SEQ/128, NHEAD), 256, HG_SMEM>>>(
        p_hprobs, T_SEQ, (long long)T_SEQ*T_SEQ,
        p_hcompT, T_SEQ, 0,
        p_hol, KV_LORA, (long long)T_SEQ*KV_LORA,
        T_SEQ, KV_LORA, T_SEQ, F_KCAUSAL | F_HALFOUT);

    // o_v[:, h*128:(h+1)*128] = O[h] @ w_uv[:,h,:]  -> f16
    hgemm<<<dim3(1, T_SEQ/128, NHEAD), 256, HG_SMEM>>>(
        p_hol, KV_LORA, (long long)T_SEQ*KV_LORA,
        p_wuvT, KV_LORA, (long long)D_V*KV_LORA,
        p_hov, NHEAD*D_V, (long long)D_V,
        T_SEQ, D_V, KV_LORA, F_HALFOUT);

    // out = o_v @ w_o (f32)
    hgemm<<<dim3(HID/128, T_SEQ/128, 1), 256, HG_SMEM>>>(
        p_hov, NHEAD*D_V, 0, p_woT, NHEAD*D_V, 0, out, HID, 0,
        T_SEQ, HID, NHEAD*D_V, 0);
}

// round 13
// speedup vs baseline: 1.2243x; 1.0926x over previous
#include <cuda_runtime.h>
#include <cuda_fp16.h>
#include <math.h>
#include <stdint.h>

#define T_SEQ   2048
#define HID     4096
#define NHEAD   32
#define Q_LORA  1536
#define KV_LORA 512
#define D_NOPE  128
#define D_ROPE  64
#define D_QK    192
#define D_V     128
#define D_AUG   576
#define EPS_RMS 1e-6f

#define F_KCAUSAL 1   // K_eff = row0 + 128 (PV with zero-padded P)
#define F_SKIP    4   // skip blocks fully above causal diagonal
#define F_HALFOUT 8   // C is __half*

// ---------------- scratch (device globals) ----------------
__device__ float  g_qc    [T_SEQ * Q_LORA];
__device__ float  g_q     [T_SEQ * NHEAD * D_QK];
__device__ float  g_kva   [T_SEQ * D_AUG];
__device__ float  g_caug  [T_SEQ * D_AUG];

__device__ __half h_hs    [T_SEQ * HID];
__device__ __half h_qc    [T_SEQ * Q_LORA];
__device__ __half h_q     [T_SEQ * NHEAD * D_QK];
__device__ __half h_wuk   [KV_LORA * NHEAD * D_NOPE];            // [r][h][d]
__device__ __half h_qaug  [(size_t)NHEAD * T_SEQ * D_AUG];       // [h][t][576]
__device__ __half h_caug  [T_SEQ * D_AUG];                       // [s][576]
__device__ __half h_compT [KV_LORA * T_SEQ];                     // [r][s]
__device__ __half h_probs [(size_t)NHEAD * T_SEQ * T_SEQ];       // [h][t][s] scores->probs in place
__device__ __half h_ol    [(size_t)NHEAD * T_SEQ * KV_LORA];     // [h][t][r]
__device__ __half h_ov    [T_SEQ * NHEAD * D_V];
__device__ __half h_wqaT  [Q_LORA * HID];
__device__ __half h_wqbT  [(NHEAD*D_QK) * Q_LORA];
__device__ __half h_wkvaT [D_AUG * HID];
__device__ __half h_woT   [HID * HID];
__device__ __half h_wuvT  [NHEAD * D_V * KV_LORA];               // [h][d][r]

// ---------------- helpers ----------------
__device__ __forceinline__ uint32_t smem_u32(const void* p)
{
    uint32_t a;
    asm("{ .reg .u64 t; cvta.to.shared.u64 t, %1; cvt.u32.u64 %0, t; }" : "=r"(a) : "l"(p));
    return a;
}

__device__ __forceinline__ void mma16816(float c[4], const uint32_t a[4], const uint32_t b[2])
{
    asm volatile(
        "mma.sync.aligned.m16n8k16.row.col.f32.f16.f16.f32 "
        "{%0,%1,%2,%3}, {%4,%5,%6,%7}, {%8,%9}, {%0,%1,%2,%3};"
        : "+f"(c[0]), "+f"(c[1]), "+f"(c[2]), "+f"(c[3])
        : "r"(a[0]), "r"(a[1]), "r"(a[2]), "r"(a[3]), "r"(b[0]), "r"(b[1]));
}

#define LDSM_X4(r0, r1, r2, r3, addr) \
    asm volatile("ldmatrix.sync.aligned.m8n8.x4.shared.b16 {%0,%1,%2,%3}, [%4];" \
        : "=r"(r0), "=r"(r1), "=r"(r2), "=r"(r3) : "r"(addr))

__device__ __forceinline__ void cpa16(uint32_t dst, const void* src, int sz)
{
    asm volatile("cp.async.cg.shared.global [%0], [%1], 16, %2;"
        :: "r"(dst), "l"(src), "r"(sz) : "memory");
}

// load [128 rows][32 halves] tile into smem (stride 40 halves = 80B)
__device__ __forceinline__ void load_tile(
    const __half* __restrict__ src, int ld, int r0, int nvalid, int k0,
    uint32_t dst, int tid)
{
    const int row = tid >> 1;
    const int half32 = (tid & 1);
    const __half* g = src + (size_t)(r0 + row) * ld + k0 + half32 * 16;
    const uint32_t d = dst + row * 80 + half32 * 32;
    const int sz = ((r0 + row) < nvalid) ? 16 : 0;
    cpa16(d,      g,     sz);
    cpa16(d + 16, g + 8, sz);
}

// ============================================================================
// hgemm: 128x128 tile, BK=32, 3-stage cp.async pipeline (R8 config: 1661us)
// ============================================================================
#define STAGE_H (128 * 40)            // halves per operand per stage
#define HG_SMEM (3 * STAGE_H * 2 * 2) // bytes total (A+B, 3 stages)

__global__ void __launch_bounds__(256, 2) hgemm(
    const __half* __restrict__ A, int lda, long long sA,
    const __half* __restrict__ B, int ldb, long long sB,
    void* __restrict__ Cv, int ldc, long long sC,
    int M, int N, int K, int flags)
{
    const int row0 = blockIdx.y * 128;
    const int col0 = blockIdx.x * 128;
    if ((flags & F_SKIP) && col0 > row0 + 127) return;
    A += (long long)blockIdx.z * sA;
    B += (long long)blockIdx.z * sB;

    extern __shared__ __half dsm[];
    const uint32_t baseA = smem_u32(dsm);
    const uint32_t baseB = baseA + 3 * STAGE_H * 2;

    const int tid    = threadIdx.x;
    const int lane   = tid & 31;
    const int wid    = tid >> 5;
    const int warp_m = wid >> 2;
    const int warp_n = wid & 3;
    const int lg     = lane >> 2;
    const int lt     = lane & 3;
    const int lq     = lane >> 3;
    const int lr     = lane & 7;

    const int Keff = (flags & F_KCAUSAL) ? (row0 + 128) : K;
    const int nk   = Keff >> 5;

    float acc[4][4][4];
    #pragma unroll
    for (int i = 0; i < 4; i++)
        #pragma unroll
        for (int j = 0; j < 4; j++)
            #pragma unroll
            for (int e = 0; e < 4; e++) acc[i][j][e] = 0.f;

    // preload stages 0,1
    load_tile(A, lda, row0, M, 0, baseA, tid);
    load_tile(B, ldb, col0, N, 0, baseB, tid);
    asm volatile("cp.async.commit_group;" ::: "memory");
    if (nk > 1) {
        load_tile(A, lda, row0, M, 32, baseA + STAGE_H * 2, tid);
        load_tile(B, ldb, col0, N, 32, baseB + STAGE_H * 2, tid);
        asm volatile("cp.async.commit_group;" ::: "memory");
    }

    int sidx = 0;  // stage of tile i
    for (int i = 0; i < nk; i++) {
        // wait for tile i's group, then a single barrier.
        if (i + 1 < nk) {
            asm volatile("cp.async.wait_group 1;" ::: "memory");
        } else {
            asm volatile("cp.async.wait_group 0;" ::: "memory");
        }
        __syncthreads();
        // Safe to overwrite stage (i+2)%3 == (i-1)%3: every warp past this
        // barrier has finished compute(i-1) by program order.
        if (i + 2 < nk) {
            const int s2 = (sidx + 2) % 3;
            load_tile(A, lda, row0, M, (i + 2) * 32, baseA + s2 * STAGE_H * 2, tid);
            load_tile(B, ldb, col0, N, (i + 2) * 32, baseB + s2 * STAGE_H * 2, tid);
            asm volatile("cp.async.commit_group;" ::: "memory");
        }

        const uint32_t sA_ = baseA + sidx * STAGE_H * 2;
        const uint32_t sB_ = baseB + sidx * STAGE_H * 2;

        #pragma unroll
        for (int kk = 0; kk < 32; kk += 16) {
            uint32_t af[4][4];
            #pragma unroll
            for (int mt = 0; mt < 4; mt++) {
                const int r = warp_m * 64 + mt * 16 + (lq & 1) * 8 + lr;
                LDSM_X4(af[mt][0], af[mt][1], af[mt][2], af[mt][3],
                        sA_ + (r * 40 + kk + (lq >> 1) * 8) * 2);
            }
            uint32_t bf[2][4];
            #pragma unroll
            for (int np = 0; np < 2; np++) {
                const int n = warp_n * 32 + np * 16 + (lq >> 1) * 8 + lr;
                LDSM_X4(bf[np][0], bf[np][1], bf[np][2], bf[np][3],
                        sB_ + (n * 40 + kk + (lq & 1) * 8) * 2);
            }
            #pragma unroll
            for (int mt = 0; mt < 4; mt++)
                #pragma unroll
                for (int nt = 0; nt < 4; nt++)
                    mma16816(acc[mt][nt], af[mt], &bf[nt >> 1][(nt & 1) * 2]);
        }
        sidx = (sidx + 1) % 3;
    }

    // ---- epilogue ----
    if (flags & F_HALFOUT) {
        __half* C = (__half*)Cv + (long long)blockIdx.z * sC;
        #pragma unroll
        for (int mt = 0; mt < 4; mt++)
            #pragma unroll
            for (int nt = 0; nt < 4; nt++) {
                const int r = row0 + warp_m * 64 + mt * 16 + lg;
                const int c = col0 + warp_n * 32 + nt * 8 + 2 * lt;
                if (c + 1 < N) {
                    if (r < M)
                        *(__half2*)(C + (size_t)r * ldc + c) =
                            __floats2half2_rn(acc[mt][nt][0], acc[mt][nt][1]);
                    if (r + 8 < M)
                        *(__half2*)(C + (size_t)(r + 8) * ldc + c) =
                            __floats2half2_rn(acc[mt][nt][2], acc[mt][nt][3]);
                }
            }
    } else {
        float* C = (float*)Cv + (long long)blockIdx.z * sC;
        #pragma unroll
        for (int mt = 0; mt < 4; mt++)
            #pragma unroll
            for (int nt = 0; nt < 4; nt++) {
                const int r = row0 + warp_m * 64 + mt * 16 + lg;
                const int c = col0 + warp_n * 32 + nt * 8 + 2 * lt;
                if (c + 1 < N) {
                    if (r < M)
                        *(float2*)(C + (size_t)r * ldc + c) =
                            make_float2(acc[mt][nt][0], acc[mt][nt][1]);
                    if (r + 8 < M)
                        *(float2*)(C + (size_t)(r + 8) * ldc + c) =
                            make_float2(acc[mt][nt][2], acc[mt][nt][3]);
                }
            }
    }
}

// ============================================================================
// prep_kernel: ALL weight conversions/transposes in ONE launch (block ranges)
// ============================================================================
#define NB_HS    (T_SEQ * HID / 1024)                       // 8192  cvt hs
#define NB_WQA   ((HID/32) * (Q_LORA/32))                   // 6144  transpose
#define NB_WQB   ((Q_LORA/32) * ((NHEAD*D_QK)/32))          // 9216
#define NB_WKVA  ((HID/32) * (D_AUG/32))                    // 2304
#define NB_WO    ((HID/32) * (HID/32))                      // 16384
#define NB_WUK   (KV_LORA * NHEAD * D_NOPE / 1024)          // 2048  cvt
#define NB_WUV   (KV_LORA * NHEAD * D_V / 256)              // 8192  scatter
#define NB_TOTAL (NB_HS + NB_WQA + NB_WQB + NB_WKVA + NB_WO + NB_WUK + NB_WUV)

__device__ __forceinline__ void prep_transpose(
    const float* __restrict__ src, __half* __restrict__ dst,
    int R, int Cc, int bidx, int tid)
{
    __shared__ float t[32][33];
    const int nbx = Cc / 32;
    const int c0 = (bidx % nbx) * 32;
    const int r0 = (bidx / nbx) * 32;
    const int x = tid & 31, y0 = tid >> 5;
    #pragma unroll
    for (int j = 0; j < 32; j += 8)
        t[y0 + j][x] = src[(size_t)(r0 + y0 + j) * Cc + c0 + x];
    __syncthreads();
    #pragma unroll
    for (int j = 0; j < 32; j += 8)
        dst[(size_t)(c0 + y0 + j) * R + r0 + x] = __float2half(t[x][y0 + j]);
}

__global__ void __launch_bounds__(256) prep_kernel(
    const float* __restrict__ hs,  const float* __restrict__ w_qa,
    const float* __restrict__ w_qb, const float* __restrict__ w_kva,
    const float* __restrict__ w_o, const float* __restrict__ w_uk,
    const float* __restrict__ w_uv)
{
    int b = blockIdx.x;
    const int tid = threadIdx.x;
    if (b < NB_HS) {                               // cvt hs -> h_hs
        int i = (b * 256 + tid) * 4;
        float4 v = *(const float4*)(hs + i);
        *(__half2*)(h_hs + i)     = __floats2half2_rn(v.x, v.y);
        *(__half2*)(h_hs + i + 2) = __floats2half2_rn(v.z, v.w);
        return;
    }
    b -= NB_HS;
    if (b < NB_WQA) { prep_transpose(w_qa, h_wqaT, HID, Q_LORA, b, tid); return; }
    b -= NB_WQA;
    if (b < NB_WQB) { prep_transpose(w_qb, h_wqbT, Q_LORA, NHEAD*D_QK, b, tid); return; }
    b -= NB_WQB;
    if (b < NB_WKVA) { prep_transpose(w_kva, h_wkvaT, HID, D_AUG, b, tid); return; }
    b -= NB_WKVA;
    if (b < NB_WO) { prep_transpose(w_o, h_woT, HID, HID, b, tid); return; }
    b -= NB_WO;
    if (b < NB_WUK) {                              // cvt w_uk -> h_wuk
        int i = (b * 256 + tid) * 4;
        float4 v = *(const float4*)(w_uk + i);
        *(__half2*)(h_wuk + i)     = __floats2half2_rn(v.x, v.y);
        *(__half2*)(h_wuk + i + 2) = __floats2half2_rn(v.z, v.w);
        return;
    }
    b -= NB_WUK;
    {                                              // w_uv scatter -> h_wuvT [h][d][r]
        int idx = b * 256 + tid;
        int r = idx >> 12;
        int h = (idx >> 7) & 31;
        int d = idx & 127;
        h_wuvT[((size_t)(h * 128 + d)) * KV_LORA + r] = __float2half(w_uv[idx]);
    }
}

// ---------------- f32 -> f16 convert ----------------
__global__ void cvt_f2h(const float* __restrict__ src, __half* __restrict__ dst, int n)
{
    int i = (blockIdx.x * blockDim.x + threadIdx.x) * 4;
    if (i < n) {
        float4 v = *(const float4*)(src + i);
        *(__half2*)(dst + i)     = __floats2half2_rn(v.x, v.y);
        *(__half2*)(dst + i + 2) = __floats2half2_rn(v.z, v.w);
    }
}

// ---------------- transpose f32 -> f16 (runtime dims; used for compT) ----------------
__global__ void transpose_kh(const float* __restrict__ src, int ld_src,
                             __half* __restrict__ dst, int R, int Cc)
{
    __shared__ float t[32][33];
    const int c0 = blockIdx.x * 32, r0 = blockIdx.y * 32;
    const int x = threadIdx.x, y = threadIdx.y;
    #pragma unroll
    for (int j = 0; j < 32; j += 8) {
        int r = r0 + y + j, c = c0 + x;
        t[y + j][x] = (r < R && c < Cc) ? src[(size_t)r * ld_src + c] : 0.f;
    }
    __syncthreads();
    #pragma unroll
    for (int j = 0; j < 32; j += 8) {
        int c = c0 + y + j, r = r0 + x;
        if (c < Cc && r < R) dst[(size_t)c * R + r] = __float2half(t[x][y + j]);
    }
}

// ---------------- reductions ----------------
__device__ __forceinline__ float block_reduce_sum(float v, float* red)
{
    __syncthreads();
    const int lane = threadIdx.x & 31, wid = threadIdx.x >> 5;
    #pragma unroll
    for (int o = 16; o > 0; o >>= 1) v += __shfl_xor_sync(0xffffffffu, v, o);
    if (lane == 0) red[wid] = v;
    __syncthreads();
    const int nw = blockDim.x >> 5;
    float s = (threadIdx.x < nw) ? red[threadIdx.x] : 0.f;
    if (wid == 0) {
        #pragma unroll
        for (int o = 16; o > 0; o >>= 1) s += __shfl_xor_sync(0xffffffffu, s, o);
        if (lane == 0) red[0] = s;
    }
    __syncthreads();
    return red[0];
}

__device__ __forceinline__ float block_reduce_max(float v, float* red)
{
    __syncthreads();
    const int lane = threadIdx.x & 31, wid = threadIdx.x >> 5;
    #pragma unroll
    for (int o = 16; o > 0; o >>= 1) v = fmaxf(v, __shfl_xor_sync(0xffffffffu, v, o));
    if (lane == 0) red[wid] = v;
    __syncthreads();
    const int nw = blockDim.x >> 5;
    float s = (threadIdx.x < nw) ? red[threadIdx.x] : -3.0e38f;
    if (wid == 0) {
        #pragma unroll
        for (int o = 16; o > 0; o >>= 1) s = fmaxf(s, __shfl_xor_sync(0xffffffffu, s, o));
        if (lane == 0) red[0] = s;
    }
    __syncthreads();
    return red[0];
}

// ---------------- softmax: f16 scores -> f16 probs IN PLACE, one exp per element ----------------
__global__ void softmax_kernel()
{
    __shared__ float red[32];
    __shared__ float buf[T_SEQ];
    const int t = blockIdx.x;
    const int h = blockIdx.y;
    __half* row = h_probs + ((size_t)h * T_SEQ + t) * T_SEQ;
    const int n = t + 1;
    const float scale = rsqrtf(192.0f);

    float m = -3.0e38f;
    for (int i = threadIdx.x; i < n; i += blockDim.x) {
        float v = __half2float(row[i]) * scale;
        buf[i] = v;
        m = fmaxf(m, v);
    }
    m = block_reduce_max(m, red);

    float l = 0.f;
    for (int i = threadIdx.x; i < n; i += blockDim.x) {
        float e = __expf(buf[i] - m);
        buf[i] = e;
        l += e;
    }
    l = block_reduce_sum(l, red);
    const float inv = 1.0f / l;

    const int kblk = ((t >> 7) + 1) << 7;
    for (int i = threadIdx.x; i < kblk; i += blockDim.x)
        row[i] = __float2half((i < n) ? buf[i] * inv : 0.f);
}

// ---------------- rmsnorm: f32 in -> f16 out ----------------
__global__ void rmsnorm_h(const float* __restrict__ x, const float* __restrict__ scale,
                          __half* __restrict__ out, int N)
{
    __shared__ float red[32];
    const float* xr = x + (size_t)blockIdx.x * N;
    __half* orow = out + (size_t)blockIdx.x * N;
    float ss = 0.f;
    for (int i = threadIdx.x; i < N; i += blockDim.x) { float v = xr[i]; ss += v * v; }
    float tot = block_reduce_sum(ss, red);
    float r = rsqrtf(tot / (float)N + EPS_RMS);
    for (int i = threadIdx.x; i < N; i += blockDim.x)
        orow[i] = __float2half(xr[i] * r * scale[i]);
}

// ---------------- kv post: rmsnorm -> caug[:,0:512]; rope -> caug[:,512:576] (f32) ----------------
__global__ void kv_post_kernel(const int* __restrict__ pos, const float* __restrict__ scale)
{
    __shared__ float red[32];
    const int t = blockIdx.x;
    const float* row = g_kva + (size_t)t * D_AUG;
    float* crow = g_caug + (size_t)t * D_AUG;
    float ss = 0.f;
    for (int i = threadIdx.x; i < KV_LORA; i += blockDim.x) { float v = row[i]; ss += v * v; }
    float tot = block_reduce_sum(ss, red);
    float r = rsqrtf(tot / (float)KV_LORA + EPS_RMS);
    for (int i = threadIdx.x; i < KV_LORA; i += blockDim.x)
        crow[i] = row[i] * r * scale[i];
    if (threadIdx.x < D_ROPE / 2) {
        int i = threadIdx.x;
        float p = (float)pos[t];
        float inv = __powf(10000.0f, -(float)i * (1.0f / 32.0f));
        float ang = p * inv;
        float c = cosf(ang), s = sinf(ang);
        float x1 = row[KV_LORA + 2*i], x2 = row[KV_LORA + 2*i + 1];
        crow[KV_LORA + 2*i    ] = x1 * c - x2 * s;
        crow[KV_LORA + 2*i + 1] = x1 * s + x2 * c;
    }
}

// ---------------- fused q rope + f16 convert ----------------
__global__ void q_rope_cvt(const int* __restrict__ pos)
{
    const int t = blockIdx.x;
    const float p = (float)pos[t];
    const float* src = g_q + (size_t)t * (NHEAD * D_QK);
    __half* dst = h_q + (size_t)t * (NHEAD * D_QK);
    for (int idx = threadIdx.x; idx < NHEAD * D_QK / 2; idx += blockDim.x) {
        const int c = idx * 2;
        const int o = c % D_QK;
        float x1 = src[c], x2 = src[c + 1];
        if (o >= D_NOPE) {
            const int j = (o - D_NOPE) >> 1;
            float inv = __powf(10000.0f, -(float)j * (1.0f / 32.0f));
            float ang = p * inv;
            float cc = cosf(ang), ss = sinf(ang);
            float y1 = x1 * cc - x2 * ss;
            float y2 = x1 * ss + x2 * cc;
            x1 = y1; x2 = y2;
        }
        *(__half2*)(dst + c) = __floats2half2_rn(x1, x2);
    }
}

// ---------------- copy roped q into h_qaug[:, 512:576] ----------------
__global__ void qaug_rope_kernel()
{
    const int t = blockIdx.x;
    for (int idx = threadIdx.x; idx < NHEAD * D_ROPE; idx += blockDim.x) {
        int h = idx >> 6, k = idx & 63;
        h_qaug[((size_t)h * T_SEQ + t) * D_AUG + KV_LORA + k] =
            h_q[(size_t)t * (NHEAD * D_QK) + h * D_QK + D_NOPE + k];
    }
}

// ---------------- host launcher ----------------
extern "C" void kernel_launch(void* const* d_in, const int* in_sizes, int n_in,
                              void* d_out, int out_size)
{
    const float* hs     = (const float*)d_in[0];
    const int*   pos    = (const int*)  d_in[1];
    const float* w_qa   = (const float*)d_in[2];
    const float* qa_ln  = (const float*)d_in[3];
    const float* w_qb   = (const float*)d_in[4];
    const float* w_kva  = (const float*)d_in[5];
    const float* kva_ln = (const float*)d_in[6];
    const float* w_uk   = (const float*)d_in[7];
    const float* w_uv   = (const float*)d_in[8];
    const float* w_o    = (const float*)d_in[9];
    float* out = (float*)d_out;

    float  *p_qc, *p_q, *p_kva, *p_caug;
    __half *p_hs, *p_hqc, *p_hq, *p_hwuk, *p_hqaug, *p_hcaug, *p_hcompT,
           *p_hprobs, *p_hol, *p_hov, *p_wqaT, *p_wqbT, *p_wkvaT, *p_woT, *p_wuvT;
    cudaGetSymbolAddress((void**)&p_qc,     g_qc);
    cudaGetSymbolAddress((void**)&p_q,      g_q);
    cudaGetSymbolAddress((void**)&p_kva,    g_kva);
    cudaGetSymbolAddress((void**)&p_caug,   g_caug);
    cudaGetSymbolAddress((void**)&p_hs,     h_hs);
    cudaGetSymbolAddress((void**)&p_hqc,    h_qc);
    cudaGetSymbolAddress((void**)&p_hq,     h_q);
    cudaGetSymbolAddress((void**)&p_hwuk,   h_wuk);
    cudaGetSymbolAddress((void**)&p_hqaug,  h_qaug);
    cudaGetSymbolAddress((void**)&p_hcaug,  h_caug);
    cudaGetSymbolAddress((void**)&p_hcompT, h_compT);
    cudaGetSymbolAddress((void**)&p_hprobs, h_probs);
    cudaGetSymbolAddress((void**)&p_hol,    h_ol);
    cudaGetSymbolAddress((void**)&p_hov,    h_ov);
    cudaGetSymbolAddress((void**)&p_wqaT,   h_wqaT);
    cudaGetSymbolAddress((void**)&p_wqbT,   h_wqbT);
    cudaGetSymbolAddress((void**)&p_wkvaT,  h_wkvaT);
    cudaGetSymbolAddress((void**)&p_woT,    h_woT);
    cudaGetSymbolAddress((void**)&p_wuvT,   h_wuvT);

    cudaFuncSetAttribute(hgemm, cudaFuncAttributeMaxDynamicSharedMemorySize, HG_SMEM);

    // one fused prep launch (all conversions + weight transposes)
    prep_kernel<<<NB_TOTAL, 256>>>(hs, w_qa, w_qb, w_kva, w_o, w_uk, w_uv);

    // q_c = rmsnorm(hs @ w_qa) -> f16
    hgemm<<<dim3(Q_LORA/128, T_SEQ/128, 1), 256, HG_SMEM>>>(
        p_hs, HID, 0, p_wqaT, HID, 0, p_qc, Q_LORA, 0, T_SEQ, Q_LORA, HID, 0);
    rmsnorm_h<<<T_SEQ, 256>>>(p_qc, qa_ln, p_hqc, Q_LORA);

    // q = q_c @ w_qb (f32), fused rope + convert -> h_q
    hgemm<<<dim3((NHEAD*D_QK)/128, T_SEQ/128, 1), 256, HG_SMEM>>>(
        p_hqc, Q_LORA, 0, p_wqbT, Q_LORA, 0, p_q, NHEAD*D_QK, 0,
        T_SEQ, NHEAD*D_QK, Q_LORA, 0);
    q_rope_cvt<<<T_SEQ, 256>>>(pos);

    // qaug[h][:,0:512] = q_nope[:,h,:] @ w_uk[:,h,:]^T  -> f16  (ncu -s 5 lands here)
    hgemm<<<dim3(KV_LORA/128, T_SEQ/128, NHEAD), 256, HG_SMEM>>>(
        p_hq, NHEAD*D_QK, (long long)D_QK,
        p_hwuk, NHEAD*D_NOPE, (long long)D_NOPE,
        p_hqaug, D_AUG, (long long)T_SEQ*D_AUG,
        T_SEQ, KV_LORA, D_NOPE, F_HALFOUT);
    qaug_rope_kernel<<<T_SEQ, 256>>>();

    // kv_a = hs @ w_kva (f32), then rmsnorm+rope -> caug f32 -> f16 (+transposed)
    hgemm<<<dim3((D_AUG+127)/128, T_SEQ/128, 1), 256, HG_SMEM>>>(
        p_hs, HID, 0, p_wkvaT, HID, 0, p_kva, D_AUG, 0, T_SEQ, D_AUG, HID, 0);
    kv_post_kernel<<<T_SEQ, 256>>>(pos, kva_ln);
    cvt_f2h<<<(T_SEQ*D_AUG/4 + 255)/256, 256>>>(p_caug, p_hcaug, T_SEQ*D_AUG);
    transpose_kh<<<dim3(KV_LORA/32, T_SEQ/32), dim3(32, 8)>>>(p_caug, D_AUG, p_hcompT, T_SEQ, KV_LORA);

    // scores[h] = Qaug[h] @ Caug^T -> f16 directly into h_probs (causal skip)
    hgemm<<<dim3(T_SEQ/128, T_SEQ/128, NHEAD), 256, HG_SMEM>>>(
        p_hqaug, D_AUG, (long long)T_SEQ*D_AUG,
        p_hcaug, D_AUG, 0,
        p_hprobs, T_SEQ, (long long)T_SEQ*T_SEQ,
        T_SEQ, T_SEQ, D_AUG, F_SKIP | F_HALFOUT);

    // softmax in place on h_probs (zero-pads to 128 boundary)
    softmax_kernel<<<dim3(T_SEQ, NHEAD), 256>>>();

    // O[h] = P[h] @ comp  -> f16 (K capped at row0+128)
    hgemm<<<dim3(KV_LORA/128, T_SEQ/128, NHEAD), 256, HG_SMEM>>>(
        p_hprobs, T_SEQ, (long long)T_SEQ*T_SEQ,
        p_hcompT, T_SEQ, 0,
        p_hol, KV_LORA, (long long)T_SEQ*KV_LORA,
        T_SEQ, KV_LORA, T_SEQ, F_KCAUSAL | F_HALFOUT);

    // o_v[:, h*128:(h+1)*128] = O[h] @ w_uv[:,h,:]  -> f16
    hgemm<<<dim3(1, T_SEQ/128, NHEAD), 256, HG_SMEM>>>(
        p_hol, KV_LORA, (long long)T_SEQ*KV_LORA,
        p_wuvT, KV_LORA, (long long)D_V*KV_LORA,
        p_hov, NHEAD*D_V, (long long)D_V,
        T_SEQ, D_V, KV_LORA, F_HALFOUT);

    // out = o_v @ w_o (f32)
    hgemm<<<dim3(HID/128, T_SEQ/128, 1), 256, HG_SMEM>>>(
        p_hov, NHEAD*D_V, 0, p_woT, NHEAD*D_V, 0, out, HID, 0,
        T_SEQ, HID, NHEAD*D_V, 0);
}